// round 2
// baseline (speedup 1.0000x reference)
#include <cuda_runtime.h>

// DILATE loss: 0.5 * softDTW(D).sum()/B + 0.5 * (E * Omega).sum()/(B*T*T)
// B=64, T=128, C=4 -> M=256 independent 128x128 soft-DTW problems, gamma=0.01.
// One CTA (128 threads) per series. Full R matrix in dynamic SMEM (129x130,
// stride 130 => conflict-free diagonal access). Forward anti-diagonal wavefront,
// then analytic backward E-recursion with rolling diagonal buffers, fused
// temporal-penalty accumulation. Deterministic final reduce kernel.

#define NT    128
#define NN    128
#define RS    130
#define BV    64
#define CC    4
#define MM    256
#define GAMMA 0.01f
#define INVG  100.0f
#define BIGV  1.0e8f

__device__ float g_partial[MM];

__global__ __launch_bounds__(128, 3)
void dilate_main_kernel(const float* __restrict__ outputs,
                        const float* __restrict__ targets) {
    extern __shared__ float sm[];
    float* R  = sm;               // 129*130 = 16770 floats
    float* ts = sm + 16770;       // 128
    float* os = ts + NN;          // 128
    float* eb = os + NN;          // 3*132 rolling E diagonals
    __shared__ float red[4];

    const int tid = threadIdx.x;
    const int m   = blockIdx.x;
    const int b   = m >> 2;       // series m = b*C + c
    const int c   = m & 3;

    // Load the two length-128 series (strided gmem, tiny traffic).
    ts[tid] = targets[(b * NT + tid) * CC + c];
    os[tid] = outputs[(b * NT + tid) * CC + c];

    const int i = tid + 1;        // DP row handled by this thread (1..128)
    // Boundary conditions.
    R[i * RS + 0] = BIGV;
    R[0 * RS + i] = BIGV;
    if (tid == 0) R[0] = 0.0f;
    // Zero E rolling buffers (3 x 132 floats, contiguous).
    for (int k = tid; k < 3 * 132; k += NT) eb[k] = 0.0f;
    __syncthreads();

    const float ti = ts[tid];     // t[i]  (1-indexed i -> ts[i-1])

    // ---------------- Forward: R[i][j] = D + softmin(R[i-1][j-1], R[i-1][j], R[i][j-1])
    for (int d = 2; d <= 2 * NN; ++d) {
        int j = d - i;
        if (j >= 1 && j <= NN) {
            float oj = os[j - 1];
            float dv = ti - oj; dv *= dv;
            float r00 = R[(i - 1) * RS + (j - 1)];
            float r01 = R[(i - 1) * RS + j];
            float r10 = R[i * RS + (j - 1)];
            float mn = fminf(r00, fminf(r01, r10));
            float s = __expf((mn - r00) * INVG)
                    + __expf((mn - r01) * INVG)
                    + __expf((mn - r10) * INVG);
            R[i * RS + j] = dv + mn - GAMMA * __logf(s);
        }
        __syncthreads();
    }

    // ---------------- Backward: E[i][j] = wa*E[i+1][j] + wb*E[i][j+1] + wc*E[i+1][j+1]
    // wa = exp((R[i+1][j]   - R[i][j] - D[i+1][j]  ) / g), etc.
    float* p2 = eb;               // diag d+2
    float* p1 = eb + 132;         // diag d+1
    float* cu = eb + 264;         // diag d (being written)
    if (tid == 0) p1[NN] = 1.0f;  // E[N][N] = 1 (seed at diag 2N)
    __syncthreads();

    float tsum = 0.0f;
    const float tip1 = (i < NN) ? ts[i] : 0.0f;   // t[i+1]

    for (int d = 2 * NN - 1; d >= 2; --d) {
        int j = d - i;
        float E = 0.0f;
        if (j >= 1 && j <= NN) {
            float rij = R[i * RS + j];
            float oj  = os[j - 1];
            if (i < NN) {
                float dn = tip1 - oj; dn *= dn;
                E += __expf((R[(i + 1) * RS + j] - rij - dn) * INVG) * p1[i + 1];
            }
            if (j < NN) {
                float ojn = os[j];
                float dn = ti - ojn; dn *= dn;
                E += __expf((R[i * RS + (j + 1)] - rij - dn) * INVG) * p1[i];
                if (i < NN) {
                    float dn2 = tip1 - ojn; dn2 *= dn2;
                    E += __expf((R[(i + 1) * RS + (j + 1)] - rij - dn2) * INVG) * p2[i + 1];
                }
            }
            float dd = (float)(i - j);
            tsum += E * dd * dd;
        }
        cu[i] = E;                // invalid cells store 0; idx 0 / >=129 stay 0 from init
        __syncthreads();
        float* tmp = p2; p2 = p1; p1 = cu; cu = tmp;
    }

    // ---------------- Block reduce tsum; combine with R[N][N].
    #pragma unroll
    for (int o = 16; o; o >>= 1)
        tsum += __shfl_xor_sync(0xffffffffu, tsum, o);
    if ((tid & 31) == 0) red[tid >> 5] = tsum;
    __syncthreads();
    if (tid == 0) {
        float tt  = red[0] + red[1] + red[2] + red[3];
        float rnn = R[NN * RS + NN];
        // ALPHA = 0.5: 0.5*rnn/B + 0.5*tsum/(B*T*T)
        g_partial[m] = 0.5f * rnn * (1.0f / BV)
                     + 0.5f * tt  * (1.0f / (BV * (float)NT * (float)NT));
    }
}

__global__ void dilate_reduce_kernel(float* __restrict__ out) {
    __shared__ float s[MM];
    int t = threadIdx.x;
    s[t] = g_partial[t];
    __syncthreads();
    #pragma unroll
    for (int o = MM / 2; o; o >>= 1) {
        if (t < o) s[t] += s[t + o];
        __syncthreads();
    }
    if (t == 0) out[0] = s[0];
}

extern "C" void kernel_launch(void* const* d_in, const int* in_sizes, int n_in,
                              void* d_out, int out_size) {
    const float* outputs = (const float*)d_in[0];
    const float* targets = (const float*)d_in[1];
    float* out = (float*)d_out;

    const int smem_bytes = (16770 + 128 + 128 + 3 * 132) * (int)sizeof(float);
    cudaFuncSetAttribute(dilate_main_kernel,
                         cudaFuncAttributeMaxDynamicSharedMemorySize, smem_bytes);

    dilate_main_kernel<<<MM, 128, smem_bytes>>>(outputs, targets);
    dilate_reduce_kernel<<<1, MM>>>(out);
}

// round 3
// speedup vs baseline: 1.0046x; 1.0046x over previous
#include <cuda_runtime.h>

// DILATE loss: 0.5 * softDTW(D).sum()/B + 0.5 * (E * Omega).sum()/(B*T*T)
// B=64, T=128, C=4 -> M=256 independent 128x128 soft-DTW problems, gamma=0.01.
// One CTA (128 threads) per series. Full R matrix in dynamic SMEM (129x130,
// stride 130 => conflict-free diagonal access). Forward anti-diagonal wavefront,
// then analytic backward E-recursion with rolling diagonal buffers, fused
// temporal-penalty accumulation. Deterministic final reduce kernel.

#define NT    128
#define NN    128
#define RS    130
#define BV    64
#define CC    4
#define MM    256
#define GAMMA 0.01f
#define INVG  100.0f
#define BIGV  1.0e8f

__device__ float g_partial[MM];

__global__ __launch_bounds__(128, 3)
void dilate_main_kernel(const float* __restrict__ outputs,
                        const float* __restrict__ targets) {
    extern __shared__ float sm[];
    float* R  = sm;               // 129*130 = 16770 floats
    float* ts = sm + 16770;       // 128
    float* os = ts + NN;          // 128
    float* eb = os + NN;          // 3*132 rolling E diagonals
    __shared__ float red[4];

    const int tid = threadIdx.x;
    const int m   = blockIdx.x;
    const int b   = m >> 2;       // series m = b*C + c
    const int c   = m & 3;

    // Load the two length-128 series (strided gmem, tiny traffic).
    ts[tid] = targets[(b * NT + tid) * CC + c];
    os[tid] = outputs[(b * NT + tid) * CC + c];

    const int i = tid + 1;        // DP row handled by this thread (1..128)
    // Boundary conditions.
    R[i * RS + 0] = BIGV;
    R[0 * RS + i] = BIGV;
    if (tid == 0) R[0] = 0.0f;
    // Zero E rolling buffers (3 x 132 floats, contiguous).
    for (int k = tid; k < 3 * 132; k += NT) eb[k] = 0.0f;
    __syncthreads();

    const float ti = ts[tid];     // t[i]  (1-indexed i -> ts[i-1])

    // ---------------- Forward: R[i][j] = D + softmin(R[i-1][j-1], R[i-1][j], R[i][j-1])
    for (int d = 2; d <= 2 * NN; ++d) {
        int j = d - i;
        if (j >= 1 && j <= NN) {
            float oj = os[j - 1];
            float dv = ti - oj; dv *= dv;
            float r00 = R[(i - 1) * RS + (j - 1)];
            float r01 = R[(i - 1) * RS + j];
            float r10 = R[i * RS + (j - 1)];
            float mn = fminf(r00, fminf(r01, r10));
            float s = __expf((mn - r00) * INVG)
                    + __expf((mn - r01) * INVG)
                    + __expf((mn - r10) * INVG);
            R[i * RS + j] = dv + mn - GAMMA * __logf(s);
        }
        __syncthreads();
    }

    // ---------------- Backward: E[i][j] = wa*E[i+1][j] + wb*E[i][j+1] + wc*E[i+1][j+1]
    // wa = exp((R[i+1][j]   - R[i][j] - D[i+1][j]  ) / g), etc.
    float* p2 = eb;               // diag d+2
    float* p1 = eb + 132;         // diag d+1
    float* cu = eb + 264;         // diag d (being written)
    if (tid == 0) p1[NN] = 1.0f;  // E[N][N] = 1 (seed at diag 2N)
    __syncthreads();

    float tsum = 0.0f;
    const float tip1 = (i < NN) ? ts[i] : 0.0f;   // t[i+1]

    for (int d = 2 * NN - 1; d >= 2; --d) {
        int j = d - i;
        float E = 0.0f;
        if (j >= 1 && j <= NN) {
            float rij = R[i * RS + j];
            float oj  = os[j - 1];
            if (i < NN) {
                float dn = tip1 - oj; dn *= dn;
                E += __expf((R[(i + 1) * RS + j] - rij - dn) * INVG) * p1[i + 1];
            }
            if (j < NN) {
                float ojn = os[j];
                float dn = ti - ojn; dn *= dn;
                E += __expf((R[i * RS + (j + 1)] - rij - dn) * INVG) * p1[i];
                if (i < NN) {
                    float dn2 = tip1 - ojn; dn2 *= dn2;
                    E += __expf((R[(i + 1) * RS + (j + 1)] - rij - dn2) * INVG) * p2[i + 1];
                }
            }
            float dd = (float)(i - j);
            tsum += E * dd * dd;
        }
        cu[i] = E;                // invalid cells store 0; idx 0 / >=129 stay 0 from init
        __syncthreads();
        float* tmp = p2; p2 = p1; p1 = cu; cu = tmp;
    }

    // ---------------- Block reduce tsum; combine with R[N][N].
    #pragma unroll
    for (int o = 16; o; o >>= 1)
        tsum += __shfl_xor_sync(0xffffffffu, tsum, o);
    if ((tid & 31) == 0) red[tid >> 5] = tsum;
    __syncthreads();
    if (tid == 0) {
        float tt  = red[0] + red[1] + red[2] + red[3];
        float rnn = R[NN * RS + NN];
        // ALPHA = 0.5: 0.5*rnn/B + 0.5*tsum/(B*T*T)
        g_partial[m] = 0.5f * rnn * (1.0f / BV)
                     + 0.5f * tt  * (1.0f / (BV * (float)NT * (float)NT));
    }
}

__global__ void dilate_reduce_kernel(float* __restrict__ out) {
    __shared__ float s[MM];
    int t = threadIdx.x;
    s[t] = g_partial[t];
    __syncthreads();
    #pragma unroll
    for (int o = MM / 2; o; o >>= 1) {
        if (t < o) s[t] += s[t + o];
        __syncthreads();
    }
    if (t == 0) out[0] = s[0];
}

extern "C" void kernel_launch(void* const* d_in, const int* in_sizes, int n_in,
                              void* d_out, int out_size) {
    const float* outputs = (const float*)d_in[0];
    const float* targets = (const float*)d_in[1];
    float* out = (float*)d_out;

    const int smem_bytes = (16770 + 128 + 128 + 3 * 132) * (int)sizeof(float);
    cudaFuncSetAttribute(dilate_main_kernel,
                         cudaFuncAttributeMaxDynamicSharedMemorySize, smem_bytes);

    dilate_main_kernel<<<MM, 128, smem_bytes>>>(outputs, targets);
    dilate_reduce_kernel<<<1, MM>>>(out);
}